// round 16
// baseline (speedup 1.0000x reference)
#include <cuda_runtime.h>
#include <math.h>

// ---------------------------------------------------------------------------
// NoisyTopkRouter: B=128, T1=128, T2=8, D=1024, E=64
// SINGLE kernel, 148 CTAs x 1024 threads (one per SM):
//  - CTAs 0..127 ("batch CTAs"): stream rows [0,896) of their batch (3.5MB),
//    then spin (R12-proven acquire protocol) for their tail partial, add it,
//    reduce, and run the proven GEMV + softmax/rank/pad-quirk chain.
//  - CTAs 128..147 ("helpers"): stream the 128-row tails of 6-7 batches each
//    (<=896 rows, balanced), store per-thread partials to g_tail[b][tid],
//    release via __threadfence + atomicExch(flag=1).
//  All 148 SMs stream ~equal bytes -> per-SM-rate-bound time drops ~12.5%.
//  Flags self-reset (batch CTA exchanges back to 0) -> replay-deterministic.
// Outputs: router_output [B,E] then noisy [B,E].
// ---------------------------------------------------------------------------

#define B_ 128
#define TT 1024   // T1*T2
#define D_ 1024
#define E_ 64
#define MAIN_ROWS 896               // rows streamed by the batch CTA
#define TAIL_ROWS (TT - MAIN_ROWS)  // 128 rows streamed by a helper
#define NHELP 20
#define NCTA (B_ + NHELP)           // 148

// tail partials: [B][1024] float4 = 2 MiB ; flags zero-init at load
__device__ float4 g_tail[B_ * 1024];
__device__ int    g_flag[B_];

__device__ __forceinline__ float softplus_f(float x) {
    // jax.nn.softplus = logaddexp(x, 0)
    return fmaxf(x, 0.f) + log1pf(expf(-fabsf(x)));
}

__device__ __forceinline__ int ld_acquire_gpu(const int* p) {
    int v;
    asm volatile("ld.acquire.gpu.b32 %0, [%1];" : "=r"(v) : "l"(p) : "memory");
    return v;
}

__global__ void __launch_bounds__(1024) fused_batch_kernel(
    const float* __restrict__ mh,
    const float* __restrict__ W_route, const float* __restrict__ b_route,
    const float* __restrict__ W_noise, const float* __restrict__ b_noise,
    const float* __restrict__ noise_eps, const int* __restrict__ mis_mask,
    float* __restrict__ out, int out_size)
{
    __shared__ __align__(16) float4 sbuf[1024];     // 16 KB reduce buffer
    __shared__ __align__(16) float pooled[D_];      // 4 KB pooled vector
    __shared__ float lraw[E_], nraw[E_];
    __shared__ float ebuf1[E_], ebuf2[E_];
    __shared__ float noisy_s[E_], sparse_s[E_];

    const int bid = blockIdx.x;
    const int tid = threadIdx.x;
    const int r0  = tid >> 8;        // row-class 0..3
    const int c   = tid & 255;       // float4 column

    // ================= helper CTAs: stream batch tails =================
    if (bid >= B_) {
        const int h  = bid - B_;
        const int bs = (B_ * h) / NHELP;
        const int be = (B_ * (h + 1)) / NHELP;
        for (int bb = bs; bb < be; ++bb) {
            const float4* base = reinterpret_cast<const float4*>(mh)
                               + ((size_t)bb * TT + MAIN_ROWS + r0) * (D_ / 4) + c;
            float4 acc = make_float4(0.f, 0.f, 0.f, 0.f);
#pragma unroll 8
            for (int i = 0; i < TAIL_ROWS / 4; ++i) {
                float4 v = __ldcs(base + (size_t)i * D_);
                acc.x += v.x; acc.y += v.y; acc.z += v.z; acc.w += v.w;
            }
            g_tail[bb * 1024 + tid] = acc;
            __syncthreads();         // all tail stores issued
            __threadfence();         // release: visible device-wide
            if (tid == 0) atomicExch(&g_flag[bb], 1);
        }
        return;
    }

    // ================= batch CTAs =================
    const int b = bid;
    float4 acc;

    // --- phase 1: stream rows [0, MAIN_ROWS) of this batch (3.5 MB) ---
    {
        const float4* base = reinterpret_cast<const float4*>(mh)
                           + ((size_t)b * TT + r0) * (D_ / 4) + c;
        acc = make_float4(0.f, 0.f, 0.f, 0.f);
#pragma unroll 8
        for (int i = 0; i < MAIN_ROWS / 4; ++i) {
            float4 v = __ldcs(base + (size_t)i * D_);  // +4 rows per step
            acc.x += v.x; acc.y += v.y; acc.z += v.z; acc.w += v.w;
        }
    }

    // warm this CTA's 4KB W slice into L2 (128 CTAs cover all 512KB)
    {
        const char* wr = reinterpret_cast<const char*>(W_route) + (size_t)b * 2048;
        const char* wn = reinterpret_cast<const char*>(W_noise) + (size_t)b * 2048;
        if (tid < 16)
            asm volatile("prefetch.global.L2 [%0];" :: "l"(wr + (size_t)tid * 128));
        else if (tid < 32)
            asm volatile("prefetch.global.L2 [%0];" :: "l"(wn + (size_t)(tid - 16) * 128));
    }

    // --- wait for tail partial (R12-proven acquire protocol) ---
    if (tid == 0) {
        while (ld_acquire_gpu(&g_flag[b]) == 0)
            __nanosleep(32);
        atomicExch(&g_flag[b], 0);   // reset for next replay
    }
    __syncthreads();
    __threadfence();                 // order tail reads after observed release

    // --- add tail partial, stash in reduce buffer ---
    {
        float4 t = __ldcg(&g_tail[b * 1024 + tid]);
        acc.x += t.x; acc.y += t.y; acc.z += t.z; acc.w += t.w;
        sbuf[tid] = acc;
    }
    __syncthreads();

    // ---------------- reduce 4 row-classes -> pooled ----------------
    if (tid < 256) {
        float4 s = sbuf[tid];
        float4 v1 = sbuf[256 + tid];
        float4 v2 = sbuf[512 + tid];
        float4 v3 = sbuf[768 + tid];
        s.x += v1.x + v2.x + v3.x;
        s.y += v1.y + v2.y + v3.y;
        s.z += v1.z + v2.z + v3.z;
        s.w += v1.w + v2.w + v3.w;
        const float inv = 1.0f / (float)TT;
        reinterpret_cast<float4*>(pooled)[tid] =
            make_float4(s.x * inv, s.y * inv, s.z * inv, s.w * inv);
    }
    __syncthreads();

    // ---------------- dual GEMV: warp w -> experts w and w+32 ----------------
    {
        const int w = tid >> 5, lane = tid & 31;
        const float4* pooled4 = reinterpret_cast<const float4*>(pooled);
#pragma unroll
        for (int ei = 0; ei < 2; ++ei) {
            const int e = w + ei * 32;
            const float4* wr = reinterpret_cast<const float4*>(W_route) + (size_t)e * (D_ / 4);
            const float4* wn = reinterpret_cast<const float4*>(W_noise) + (size_t)e * (D_ / 4);
            float ar = 0.f, an = 0.f;
#pragma unroll
            for (int j = lane; j < D_ / 4; j += 32) {
                float4 pv = pooled4[j];
                float4 a  = __ldg(wr + j);
                float4 cc = __ldg(wn + j);
                ar += pv.x * a.x + pv.y * a.y + pv.z * a.z + pv.w * a.w;
                an += pv.x * cc.x + pv.y * cc.y + pv.z * cc.z + pv.w * cc.w;
            }
#pragma unroll
            for (int o = 16; o; o >>= 1) {
                ar += __shfl_xor_sync(0xffffffffu, ar, o);
                an += __shfl_xor_sync(0xffffffffu, an, o);
            }
            if (lane == 0) {
                lraw[e] = ar + b_route[e];
                nraw[e] = an + b_noise[e];
            }
        }
    }
    __syncthreads();

    // ---------------- per-expert scalar chain (tid<64 active) ----------------
    float logit = 0.f;

    if (tid < E_) {
        float m1 = -INFINITY;
#pragma unroll
        for (int j = 0; j < E_; ++j) m1 = fmaxf(m1, lraw[j]);
        ebuf1[tid] = expf(lraw[tid] - m1);
        nraw[tid] = noise_eps[b * E_ + tid] * softplus_f(nraw[tid]);
    }
    __syncthreads();

    if (tid < E_) {
        float s1 = 0.f;
#pragma unroll
        for (int j = 0; j < E_; ++j) s1 += ebuf1[j];
        logit = ebuf1[tid] / s1;

        float m2 = -INFINITY;
#pragma unroll
        for (int j = 0; j < E_; ++j) m2 = fmaxf(m2, nraw[j]);
        ebuf2[tid] = expf(nraw[tid] - m2);
    }
    __syncthreads();

    if (tid < E_) {
        float s2 = 0.f;
#pragma unroll
        for (int j = 0; j < E_; ++j) s2 += ebuf2[j];
        float noisy = logit + ebuf2[tid] / s2;
        noisy_s[tid] = noisy;
        if (out_size >= 2 * B_ * E_)
            out[B_ * E_ + b * E_ + tid] = noisy;   // second output: noisy
    }
    __syncthreads();

    if (tid < E_) {
        // stable descending rank (ties -> lower index first)
        const float myv = noisy_s[tid];
        int rank = 0;
#pragma unroll
        for (int j = 0; j < E_; ++j) {
            float vj = noisy_s[j];
            rank += (vj > myv) || (vj == myv && j < tid);
        }
        const int k = mis_mask[b];
        float sp = (rank < k) ? myv : 0.f;
        if (k < E_ && tid == 0) sp = 0.f;   // torch pad-scatter quirk
        sparse_s[tid] = sp;
    }
    __syncthreads();

    if (tid < E_) {
        float m3 = -INFINITY;
#pragma unroll
        for (int j = 0; j < E_; ++j) m3 = fmaxf(m3, sparse_s[j]);
        ebuf1[tid] = expf(sparse_s[tid] - m3);
    }
    __syncthreads();

    if (tid < E_) {
        float s3 = 0.f;
#pragma unroll
        for (int j = 0; j < E_; ++j) s3 += ebuf1[j];
        out[b * E_ + tid] = ebuf1[tid] / s3;       // first output: router_output
    }
}

extern "C" void kernel_launch(void* const* d_in, const int* in_sizes, int n_in,
                              void* d_out, int out_size) {
    const float* mh        = (const float*)d_in[0];
    const float* W_route   = (const float*)d_in[1];
    const float* b_route   = (const float*)d_in[2];
    const float* W_noise   = (const float*)d_in[3];
    const float* b_noise   = (const float*)d_in[4];
    const float* noise_eps = (const float*)d_in[5];
    const int*   mis_mask  = (const int*)d_in[6];
    float* out = (float*)d_out;

    fused_batch_kernel<<<NCTA, 1024>>>(mh, W_route, b_route, W_noise, b_noise,
                                       noise_eps, mis_mask, out, out_size);
}

// round 17
// speedup vs baseline: 1.0727x; 1.0727x over previous
#include <cuda_runtime.h>
#include <math.h>
#include <stdint.h>

// ---------------------------------------------------------------------------
// NoisyTopkRouter: B=128, T1=128, T2=8, D=1024, E=64
// SINGLE kernel, one CTA per batch (128 x 1024thr), TMA-bulk streamed:
//  - Stream: cp.async.bulk (UBLKCP) 32KB chunks into a 4-stage smem ring
//    (128KB in flight per CTA; 16MB chip-wide >> 2.4MB latency-BW product
//    that capped the LDG version at 80% DRAM-active).
//  - Consume: 1024 threads sum 2 float4/chunk from smem (conflict-free),
//    accumulation order bit-identical to the 84.7us LDG version.
//  - Then the proven reduce + GEMV + softmax/rank/pad-quirk chain in-block.
// No cross-CTA communication -> deterministic.
// Outputs: router_output [B,E] then noisy [B,E].
// ---------------------------------------------------------------------------

#define B_ 128
#define TT 1024   // T1*T2
#define D_ 1024
#define E_ 64
#define NSTAGE 4
#define CHUNK_BYTES 32768                 // 8 rows x 4KB
#define CHUNK_F4 (CHUNK_BYTES / 16)       // 2048 float4
#define NCHUNK ((TT * D_ * 4) / CHUNK_BYTES)  // 128 chunks per batch
// dynamic smem: stages (128KB) + sbuf (16KB) + pooled (4KB)
#define DSMEM_BYTES (NSTAGE * CHUNK_BYTES + 1024 * 16 + D_ * 4)

__device__ __forceinline__ uint32_t smem_u32(const void* p) {
    return (uint32_t)__cvta_generic_to_shared(p);
}

__device__ __forceinline__ float softplus_f(float x) {
    // jax.nn.softplus = logaddexp(x, 0)
    return fmaxf(x, 0.f) + log1pf(expf(-fabsf(x)));
}

__device__ __forceinline__ void mbar_init(uint32_t a, uint32_t cnt) {
    asm volatile("mbarrier.init.shared.b64 [%0], %1;" :: "r"(a), "r"(cnt) : "memory");
}
__device__ __forceinline__ void mbar_expect_tx(uint32_t a, uint32_t bytes) {
    asm volatile("mbarrier.arrive.expect_tx.shared.b64 _, [%0], %1;"
                 :: "r"(a), "r"(bytes) : "memory");
}
__device__ __forceinline__ void bulk_ld(uint32_t dst, const void* src,
                                        uint32_t bytes, uint32_t mbar) {
    asm volatile(
        "cp.async.bulk.shared::cluster.global.mbarrier::complete_tx::bytes "
        "[%0], [%1], %2, [%3];"
        :: "r"(dst), "l"(src), "r"(bytes), "r"(mbar) : "memory");
}
__device__ __forceinline__ void mbar_wait(uint32_t a, uint32_t phase) {
    asm volatile(
        "{\n\t"
        ".reg .pred P;\n\t"
        "WL_%=:\n\t"
        "mbarrier.try_wait.parity.shared::cta.b64 P, [%0], %1;\n\t"
        "@!P bra WL_%=;\n\t"
        "}"
        :: "r"(a), "r"(phase) : "memory");
}

__global__ void __launch_bounds__(1024) fused_tma_kernel(
    const float* __restrict__ mh,
    const float* __restrict__ W_route, const float* __restrict__ b_route,
    const float* __restrict__ W_noise, const float* __restrict__ b_noise,
    const float* __restrict__ noise_eps, const int* __restrict__ mis_mask,
    float* __restrict__ out, int out_size)
{
    extern __shared__ __align__(16) char dsmem[];
    float4* stages = reinterpret_cast<float4*>(dsmem);          // 4 x 2048 float4
    float4* sbuf   = stages + NSTAGE * CHUNK_F4;                // 1024 float4
    float*  pooled = reinterpret_cast<float*>(sbuf + 1024);     // 1024 floats

    __shared__ __align__(8) uint64_t full_bar[NSTAGE];
    __shared__ float lraw[E_], nraw[E_];
    __shared__ float ebuf1[E_], ebuf2[E_];
    __shared__ float noisy_s[E_], sparse_s[E_];

    const int b   = blockIdx.x;
    const int tid = threadIdx.x;

    // --- init barriers (count=1: the expect_tx arrive) ---
    if (tid == 0) {
#pragma unroll
        for (int s = 0; s < NSTAGE; ++s)
            mbar_init(smem_u32(&full_bar[s]), 1);
    }

    // --- W L2-warm: CTA b prefetches a distinct 4KB slice (all 512KB) ---
    {
        const char* wr = reinterpret_cast<const char*>(W_route) + (size_t)b * 2048;
        const char* wn = reinterpret_cast<const char*>(W_noise) + (size_t)b * 2048;
        if (tid < 16)
            asm volatile("prefetch.global.L2 [%0];" :: "l"(wr + (size_t)tid * 128));
        else if (tid < 32)
            asm volatile("prefetch.global.L2 [%0];" :: "l"(wn + (size_t)(tid - 16) * 128));
    }
    __syncthreads();
    asm volatile("fence.proxy.async.shared::cta;" ::: "memory");

    // --- prologue: fill the 4-stage ring ---
    const char* gsrc = reinterpret_cast<const char*>(mh) + (size_t)b * TT * D_ * 4;
    if (tid == 0) {
#pragma unroll
        for (int s = 0; s < NSTAGE; ++s) {
            uint32_t bar = smem_u32(&full_bar[s]);
            mbar_expect_tx(bar, CHUNK_BYTES);
            bulk_ld(smem_u32(stages + s * CHUNK_F4),
                    gsrc + (size_t)s * CHUNK_BYTES, CHUNK_BYTES, bar);
        }
    }

    // --- stream-consume: chunk k = rows [8k, 8k+8); thread sums rows
    //     8k+(tid>>8) and 8k+4+(tid>>8) at float4-column tid&255
    //     (same accumulation order as the proven LDG version) ---
    float4 acc = make_float4(0.f, 0.f, 0.f, 0.f);
#pragma unroll 1
    for (int k = 0; k < NCHUNK; ++k) {
        const int s  = k & (NSTAGE - 1);
        const int ph = (k >> 2) & 1;
        mbar_wait(smem_u32(&full_bar[s]), ph);
        const float4* buf = stages + s * CHUNK_F4;
        float4 v0 = buf[tid];
        float4 v1 = buf[tid + 1024];
        acc.x += v0.x + v1.x; acc.y += v0.y + v1.y;
        acc.z += v0.z + v1.z; acc.w += v0.w + v1.w;
        __syncthreads();   // all consumed: buffer s reusable
        if (tid == 0 && k + NSTAGE < NCHUNK) {
            uint32_t bar = smem_u32(&full_bar[s]);
            mbar_expect_tx(bar, CHUNK_BYTES);
            bulk_ld(smem_u32(stages + s * CHUNK_F4),
                    gsrc + (size_t)(k + NSTAGE) * CHUNK_BYTES, CHUNK_BYTES, bar);
        }
    }
    sbuf[tid] = acc;
    __syncthreads();

    // ---------------- reduce 4 row-classes -> pooled ----------------
    if (tid < 256) {
        float4 s = sbuf[tid];
        float4 v1 = sbuf[256 + tid];
        float4 v2 = sbuf[512 + tid];
        float4 v3 = sbuf[768 + tid];
        s.x += v1.x + v2.x + v3.x;
        s.y += v1.y + v2.y + v3.y;
        s.z += v1.z + v2.z + v3.z;
        s.w += v1.w + v2.w + v3.w;
        const float inv = 1.0f / (float)TT;
        reinterpret_cast<float4*>(pooled)[tid] =
            make_float4(s.x * inv, s.y * inv, s.z * inv, s.w * inv);
    }
    __syncthreads();

    // ---------------- dual GEMV: warp w -> experts w and w+32 ----------------
    {
        const int w = tid >> 5, lane = tid & 31;
        const float4* pooled4 = reinterpret_cast<const float4*>(pooled);
#pragma unroll
        for (int ei = 0; ei < 2; ++ei) {
            const int e = w + ei * 32;
            const float4* wr = reinterpret_cast<const float4*>(W_route) + (size_t)e * (D_ / 4);
            const float4* wn = reinterpret_cast<const float4*>(W_noise) + (size_t)e * (D_ / 4);
            float ar = 0.f, an = 0.f;
#pragma unroll
            for (int j = lane; j < D_ / 4; j += 32) {
                float4 pv = pooled4[j];
                float4 a  = __ldg(wr + j);
                float4 cc = __ldg(wn + j);
                ar += pv.x * a.x + pv.y * a.y + pv.z * a.z + pv.w * a.w;
                an += pv.x * cc.x + pv.y * cc.y + pv.z * cc.z + pv.w * cc.w;
            }
#pragma unroll
            for (int o = 16; o; o >>= 1) {
                ar += __shfl_xor_sync(0xffffffffu, ar, o);
                an += __shfl_xor_sync(0xffffffffu, an, o);
            }
            if (lane == 0) {
                lraw[e] = ar + b_route[e];
                nraw[e] = an + b_noise[e];
            }
        }
    }
    __syncthreads();

    // ---------------- per-expert scalar chain (tid<64 active) ----------------
    float logit = 0.f;

    if (tid < E_) {
        float m1 = -INFINITY;
#pragma unroll
        for (int j = 0; j < E_; ++j) m1 = fmaxf(m1, lraw[j]);
        ebuf1[tid] = expf(lraw[tid] - m1);
        nraw[tid] = noise_eps[b * E_ + tid] * softplus_f(nraw[tid]);
    }
    __syncthreads();

    if (tid < E_) {
        float s1 = 0.f;
#pragma unroll
        for (int j = 0; j < E_; ++j) s1 += ebuf1[j];
        logit = ebuf1[tid] / s1;

        float m2 = -INFINITY;
#pragma unroll
        for (int j = 0; j < E_; ++j) m2 = fmaxf(m2, nraw[j]);
        ebuf2[tid] = expf(nraw[tid] - m2);
    }
    __syncthreads();

    if (tid < E_) {
        float s2 = 0.f;
#pragma unroll
        for (int j = 0; j < E_; ++j) s2 += ebuf2[j];
        float noisy = logit + ebuf2[tid] / s2;
        noisy_s[tid] = noisy;
        if (out_size >= 2 * B_ * E_)
            out[B_ * E_ + b * E_ + tid] = noisy;   // second output: noisy
    }
    __syncthreads();

    if (tid < E_) {
        // stable descending rank (ties -> lower index first)
        const float myv = noisy_s[tid];
        int rank = 0;
#pragma unroll
        for (int j = 0; j < E_; ++j) {
            float vj = noisy_s[j];
            rank += (vj > myv) || (vj == myv && j < tid);
        }
        const int k = mis_mask[b];
        float sp = (rank < k) ? myv : 0.f;
        if (k < E_ && tid == 0) sp = 0.f;   // torch pad-scatter quirk
        sparse_s[tid] = sp;
    }
    __syncthreads();

    if (tid < E_) {
        float m3 = -INFINITY;
#pragma unroll
        for (int j = 0; j < E_; ++j) m3 = fmaxf(m3, sparse_s[j]);
        ebuf1[tid] = expf(sparse_s[tid] - m3);
    }
    __syncthreads();

    if (tid < E_) {
        float s3 = 0.f;
#pragma unroll
        for (int j = 0; j < E_; ++j) s3 += ebuf1[j];
        out[b * E_ + tid] = ebuf1[tid] / s3;       // first output: router_output
    }
}

extern "C" void kernel_launch(void* const* d_in, const int* in_sizes, int n_in,
                              void* d_out, int out_size) {
    const float* mh        = (const float*)d_in[0];
    const float* W_route   = (const float*)d_in[1];
    const float* b_route   = (const float*)d_in[2];
    const float* W_noise   = (const float*)d_in[3];
    const float* b_noise   = (const float*)d_in[4];
    const float* noise_eps = (const float*)d_in[5];
    const int*   mis_mask  = (const int*)d_in[6];
    float* out = (float*)d_out;

    // idempotent attribute set (same every call; host-side, not captured)
    cudaFuncSetAttribute(fused_tma_kernel,
                         cudaFuncAttributeMaxDynamicSharedMemorySize, DSMEM_BYTES);

    fused_tma_kernel<<<B_, 1024, DSMEM_BYTES>>>(
        mh, W_route, b_route, W_noise, b_noise,
        noise_eps, mis_mask, out, out_size);
}